// round 10
// baseline (speedup 1.0000x reference)
#include <cuda_runtime.h>
#include <math.h>

#define NMOL   32
#define NATOM  128
#define DEG    32
#define NTOT   4096
#define NPAIR  131072
#define NSENS  20
#define NF1    20
#define TM     32          // atoms owned per k_step block
#define EPS2   34          // envP row stride in u64 units (even -> 16B-aligned pairs)
#define SROW   648         // padded sense row (floats) = 162 float4

typedef unsigned long long u64t;

// ---------------- scratch (device globals; no allocation) ----------------
__device__ float  g_sense[NPAIR * NSENS];    // [pair][s]
__device__ float  g_indf [NTOT * 5];         // [atom][5]
__device__ float  g_ct   [NTOT * NF1];       // in-place (owner block only)
__device__ float  g_h    [2 * NTOT * NF1];   // parity double buffer
__device__ float  g_x0   [2 * NTOT];         // parity double buffer
__device__ float2 g_wpair [400 * 80];        // Wint paired over (s_even, s_odd)
__device__ float2 g_wspair[20 * 80];         // Wself paired over (f_even, f_odd)

__device__ __forceinline__ float softplusf(float x) {
    return fmaxf(x, 0.f) + log1pf(expf(-fabsf(x)));
}
__device__ __forceinline__ float sigmoidf(float x) {
    return 1.f / (1.f + expf(-x));
}
__device__ __forceinline__ u64t packdup(float x) {
    u64t r; asm("mov.b64 %0, {%1, %1};" : "=l"(r) : "f"(x)); return r;
}
__device__ __forceinline__ void ffma2(u64t& d, u64t a, u64t b) {
    asm("fma.rn.f32x2 %0, %1, %2, %0;" : "+l"(d) : "l"(a), "l"(b));
}
__device__ __forceinline__ void fadd2(u64t& d, u64t a) {
    asm("add.rn.f32x2 %0, %0, %1;" : "+l"(d) : "l"(a));
}
__device__ __forceinline__ void unpack2(u64t v, float& lo, float& hi) {
    asm("mov.b64 {%0, %1}, %2;" : "=f"(lo), "=f"(hi) : "l"(v));
}

// ---------------- one-time prep (merged): sense + indf + weight pairing ----------------
__global__ void k_prep(const int* __restrict__ species, const float* __restrict__ x_h,
                       const float* __restrict__ coord, const int* __restrict__ ps,
                       const float* __restrict__ Wint, const float* __restrict__ Wself) {
    int p = blockIdx.x * 256 + threadIdx.x;   // [0, NPAIR)

    // ---- sense via anchored Gaussian recurrence ----
    {
        int a = p >> 5;
        int b = ps[p];
        float dx = coord[a * 3 + 0] - coord[b * 3 + 0];
        float dy = coord[a * 3 + 1] - coord[b * 3 + 1];
        float dz = coord[a * 3 + 2] - coord[b * 3 + 2];
        float d = sqrtf(dx * dx + dy * dy + dz * dz + 1e-12f);
        float cut = 0.f;
        if (d < 7.5f) { float c = cospif(d * (1.f / 15.f)); cut = c * c; }
        const float m0 = 0.2f;
        const float m1 = 1.f / 0.7f;
        const float invsig = 20.f / (m1 - m0);
        const float delta = 20.f / 19.f;
        float z0 = (1.f / d - m0) * invsig;

        float ss = floorf(z0 / delta + 0.5f);
        ss = fminf(fmaxf(ss, 0.f), 19.f);
        int sstar = (int)ss;
        float zs = z0 - ss * delta;

        float Cd = expf(-delta * delta);
        float E  = cut * expf(-0.5f * zs * zs);
        float* o = g_sense + (size_t)p * 20;
        o[sstar] = E;
        float Eu = E;
        float uu = expf(delta * zs - 0.5f * delta * delta);
        for (int s = sstar + 1; s < 20; s++) { Eu *= uu; uu *= Cd; o[s] = Eu; }
        float Ed = E;
        float dd = expf(-delta * zs - 0.5f * delta * delta);
        for (int s = sstar - 1; s >= 0; s--) { Ed *= dd; dd *= Cd; o[s] = Ed; }
    }

    // ---- indf ----
    if (p < NTOT) {
        int sp = species[p];
        g_indf[p * 5 + 0] = (sp == 1) ? 1.f : 0.f;
        g_indf[p * 5 + 1] = (sp == 8) ? 1.f : 0.f;
        g_indf[p * 5 + 2] = x_h[p * 3 + 0];
        g_indf[p * 5 + 3] = x_h[p * 3 + 1];
        g_indf[p * 5 + 4] = x_h[p * 3 + 2];
    }

    // ---- weight pairing ----
    if (p < 32000) {
        int pr = p / 80, g = p % 80;
        int s2 = pr / 40, f = pr % 40;
        int lo = 2 * s2 * 40 + f;
        g_wpair[p] = make_float2(Wint[lo * 80 + g], Wint[(lo + 40) * 80 + g]);
    } else if (p < 32000 + 1600) {
        int i2 = p - 32000;
        int fp = i2 / 80, g = i2 % 80;
        g_wspair[i2] = make_float2(Wself[(2 * fp) * 80 + g], Wself[(2 * fp + 1) * 80 + g]);
    }
}

// ---------------- f0 hipnn (runs once, block-tiled): writes c_t, g_h[0] ----------------
#define SMEM_F0_FLOATS 37448
#define SMEM_F0_BYTES  (SMEM_F0_FLOATS * 4)

__global__ void __launch_bounds__(256, 1)
k_f0(const int* __restrict__ ps,
     const float* __restrict__ iw, const float* __restrict__ sw,
     const float* __restrict__ sb, const float* __restrict__ aw,
     const float* __restrict__ ab) {
    extern __shared__ float sm[];
    float* s_sense = sm;
    float* s_senv  = sm + 20736;
    float* s_indf  = sm + 24064;
    float* s_iw    = sm + 24704;
    float* s_sw    = sm + 28704;
    float* s_sb    = sm + 28904;
    float* s_aw    = sm + 28944;
    float* s_ab    = sm + 33744;
    float* s_sy    = sm + 33864;
    float* s_sy2   = sm + 35144;
    int*   s_nb    = (int*)(sm + 36424);

    int t  = threadIdx.x;
    int A0 = blockIdx.x * TM;
    int MB = (A0 / NATOM) * NATOM;
    int L0 = A0 - MB;

    for (int i = t; i < 1024; i += 256) s_nb[i] = ps[A0 * 32 + i] - MB;
    for (int i = t; i < 640;  i += 256) s_indf[i] = g_indf[MB * 5 + i];
    for (int i = t; i < 4000; i += 256) s_iw[i] = iw[i];
    for (int i = t; i < 4800; i += 256) s_aw[i] = aw[i];
    if (t < 200) s_sw[t] = sw[t];
    if (t >= 216 && t < 256) s_sb[t - 216] = sb[t - 216];
    for (int i = t; i < 120; i += 256) s_ab[i] = ab[i];
    {
        const float4* src = (const float4*)(g_sense + (size_t)A0 * 640);
        float4* dst = (float4*)s_sense;
        for (int q = 0; q < 20; q++) {
            int i = t + q * 256;
            int row = i / 160, col = i - row * 160;
            dst[row * 162 + col] = src[i];
        }
    }
    __syncthreads();

    {
        int aL = t >> 3;
        int r  = t & 7;
        u64t acc[10][5];
#pragma unroll
        for (int q = 0; q < 10; q++)
#pragma unroll
            for (int f = 0; f < 5; f++) acc[q][f] = 0ULL;
#pragma unroll
        for (int j = 0; j < 4; j++) {
            int k = r + j * 8;
            int nb = s_nb[aL * 32 + k];
            const float* xp = s_indf + nb * 5;
            u64t xd[5];
#pragma unroll
            for (int f = 0; f < 5; f++) xd[f] = packdup(xp[f]);
            const ulonglong2* spp = (const ulonglong2*)(s_sense + aL * SROW + k * 20);
#pragma unroll
            for (int q = 0; q < 5; q++) {
                ulonglong2 sv = spp[q];
#pragma unroll
                for (int f = 0; f < 5; f++) {
                    ffma2(acc[q * 2 + 0][f], sv.x, xd[f]);
                    ffma2(acc[q * 2 + 1][f], sv.y, xd[f]);
                }
            }
        }
#pragma unroll
        for (int d = 4; d >= 1; d >>= 1)
#pragma unroll
            for (int q = 0; q < 10; q++)
#pragma unroll
                for (int f = 0; f < 5; f++) {
                    u64t o = __shfl_down_sync(0xFFFFFFFFu, acc[q][f], d);
                    fadd2(acc[q][f], o);
                }
        if (r == 0) {
#pragma unroll
            for (int q = 0; q < 10; q++)
#pragma unroll
                for (int f = 0; f < 5; f++) {
                    float lo, hi;
                    unpack2(acc[q][f], lo, hi);
                    s_senv[aL * 104 + (2 * q)     * 5 + f] = lo;
                    s_senv[aL * 104 + (2 * q + 1) * 5 + f] = hi;
                }
        }
    }
    __syncthreads();

    {
        int a  = t >> 3;
        int j0 = (t & 7) * 5;
        float pre[5];
#pragma unroll
        for (int jj = 0; jj < 5; jj++) pre[jj] = s_sb[j0 + jj];
        const float* xo = s_indf + (L0 + a) * 5;
#pragma unroll
        for (int f = 0; f < 5; f++) {
            float xv = xo[f];
#pragma unroll
            for (int jj = 0; jj < 5; jj++) pre[jj] += xv * s_sw[f * 40 + j0 + jj];
        }
        for (int e = 0; e < 100; e++) {
            float ev = s_senv[a * 104 + e];
#pragma unroll
            for (int jj = 0; jj < 5; jj++) pre[jj] += ev * s_iw[e * 40 + j0 + jj];
        }
#pragma unroll
        for (int jj = 0; jj < 5; jj++) s_sy[a * 40 + j0 + jj] = softplusf(pre[jj]);
        __syncthreads();

        float* src = s_sy; float* dst = s_sy2;
        for (int l = 0; l < 3; l++) {
            float v[5];
#pragma unroll
            for (int jj = 0; jj < 5; jj++) v[jj] = s_ab[l * 40 + j0 + jj];
            for (int i = 0; i < 40; i++) {
                float yv = src[a * 40 + i];
#pragma unroll
                for (int jj = 0; jj < 5; jj++) v[jj] += yv * s_aw[l * 1600 + i * 40 + j0 + jj];
            }
            __syncthreads();
#pragma unroll
            for (int jj = 0; jj < 5; jj++) dst[a * 40 + j0 + jj] = softplusf(v[jj]);
            __syncthreads();
            float* tp = src; src = dst; dst = tp;
        }
        for (int idx = t; idx < 640; idx += 256) {
            int a2 = idx / 20, j = idx % 20;
            g_ct[(A0 + a2) * 20 + j] = src[a2 * 40 + j];
            g_h[(A0 + a2) * 20 + j]  = src[a2 * 40 + 20 + j];
        }
    }
}

// ---------------- fused per-step kernel: 512 threads ----------------
#define SMEM_FLOATS (5120 + 27200 + 32 * SROW + 1024 + 128 + 1700)
#define SMEM_BYTES  (SMEM_FLOATS * 4)

__global__ void __launch_bounds__(512, 1)
k_step(const int* __restrict__ ps, const float* __restrict__ x_raw, int mode,
       const float* __restrict__ h1_iw, const float* __restrict__ h1_sw,
       const float* __restrict__ h1_sb, const float* __restrict__ h1_aw,
       const float* __restrict__ h1_ab,
       const float* __restrict__ Wb,
       const float* __restrict__ pw0, const float* __restrict__ pw1,
       const float* __restrict__ pb1,
       int outcol, float* __restrict__ out, int parity) {
    extern __shared__ float sm[];
    float* s_xcat = sm;                                    // 5120
    float* s_envPf = sm + 5120;                            // 27200
    u64t*  s_envP  = (u64t*)s_envPf;                       // 13600 u64
    float* s_work = sm + 32320;                            // 20736
    int*   s_nb   = (int*)(sm + 53056);                    // 1024 ints
    float* s_xin  = sm + 54080;                            // 128
    float* s_h1w  = sm + 54208;                            // 1700
    float* s_iw = s_h1w;            // 400
    float* s_sw = s_h1w + 400;      // 20
    float* s_sb = s_h1w + 420;      // 20
    float* s_aw = s_h1w + 440;      // 1200
    float* s_ab = s_h1w + 1640;     // 60

    float* senvM = s_envPf;         // phase 2: [128][20]
    float* sy    = s_envPf + 2560;
    float* sy2   = s_envPf + 5120;
    float* s_wc  = s_work;          // GEMM W chunk (10240 floats = 64 pairs x 80 u64)
    u64t*  s_wcu = (u64t*)s_wc;
    float* s_tmp = s_work + 10240;  // 2560
    float* s_o   = s_work + 12800;  // 640

    int t  = threadIdx.x;
    int A0 = blockIdx.x * TM;
    int MB = (A0 / NATOM) * NATOM;
    int L0 = A0 - MB;
    int myc = L0 >> 5;
    const float* x0_r = g_x0 + parity * NTOT;
    float*       x0_w = g_x0 + (parity ^ 1) * NTOT;
    const float* h_r  = g_h + parity * (NTOT * NF1);
    float*       h_w  = g_h + (parity ^ 1) * (NTOT * NF1);

    // ---- stage ----
    if (t < 128) {
        int n = MB + t;
        s_xin[t] = (mode < 2) ? x_raw[n * 2 + mode] : x0_r[n];
    }
    {
        const float4* hsrc = (const float4*)(h_r + MB * NF1);
        for (int i4 = t; i4 < 640; i4 += 512) {
            int a = i4 / 5, j = (i4 % 5) * 4;
            *(float4*)&s_xcat[a * 40 + 20 + j] = hsrc[i4];
        }
    }
    for (int i = t; i < 400;  i += 512) s_iw[i] = h1_iw[i];
    for (int i = t; i < 1200; i += 512) s_aw[i] = h1_aw[i];
    if (t >= 160 && t < 180) { s_sw[t - 160] = h1_sw[t - 160]; s_sb[t - 160] = h1_sb[t - 160]; }
    if (t >= 192 && t < 252) s_ab[t - 192] = h1_ab[t - 192];
    for (int i = t; i < 1024; i += 512) s_nb[i] = ps[A0 * 32 + i] - MB;
    __syncthreads();

    // ---- phase 2a: env (f=1) for all 128 molecule atoms; 16 k-lanes/atom ----
    for (int cc = 0; cc < 4; cc++) {
        int c = (myc + 1 + cc) & 3;
        if (cc) __syncthreads();
        {
            const float4* src = (const float4*)(g_sense + (size_t)(MB + c * 32) * 640);
            float4* dst = (float4*)s_work;
            for (int q = 0; q < 10; q++) {
                int i = t + q * 512;
                int row = i / 160, col = i - row * 160;
                dst[row * 162 + col] = src[i];
            }
        }
        __syncthreads();
        int aL = t >> 4;           // atom in chunk (0..31)
        int r  = t & 15;           // k-lane (0..15)
        int aM = c * 32 + aL;
        u64t acc[10];
#pragma unroll
        for (int s = 0; s < 10; s++) acc[s] = 0ULL;
#pragma unroll
        for (int j = 0; j < 2; j++) {
            int k = r + j * 16;
            int nb = ps[(MB + aM) * 32 + k] - MB;
            u64t xd = packdup(s_xin[nb]);
            const ulonglong2* sp = (const ulonglong2*)(s_work + aL * SROW + k * 20);
#pragma unroll
            for (int q = 0; q < 5; q++) {
                ulonglong2 sv = sp[q];
                ffma2(acc[q * 2 + 0], sv.x, xd);
                ffma2(acc[q * 2 + 1], sv.y, xd);
            }
        }
#pragma unroll
        for (int d = 8; d >= 1; d >>= 1)
#pragma unroll
            for (int s = 0; s < 10; s++) {
                u64t o = __shfl_down_sync(0xFFFFFFFFu, acc[s], d, 16);
                fadd2(acc[s], o);
            }
        if (r == 0) {
#pragma unroll
            for (int s = 0; s < 10; s++) {
                float lo, hi;
                unpack2(acc[s], lo, hi);
                senvM[aM * 20 + 2 * s]     = lo;
                senvM[aM * 20 + 2 * s + 1] = hi;
            }
        }
    }
    __syncthreads();

    // ---- phase 2b: x_t MLP for all 128 atoms (4 threads/atom, 5 outputs each) ----
    {
        int a  = t >> 2;
        int sh = (t & 3) * 5;
        float xo = s_xin[a];
        float pre[5];
#pragma unroll
        for (int j = 0; j < 5; j++) pre[j] = s_sb[sh + j] + xo * s_sw[sh + j];
        for (int s2 = 0; s2 < 20; s2++) {
            float ev = senvM[a * 20 + s2];
#pragma unroll
            for (int j = 0; j < 5; j++) pre[j] += ev * s_iw[s2 * 20 + sh + j];
        }
#pragma unroll
        for (int j = 0; j < 5; j++) sy[a * 20 + sh + j] = softplusf(pre[j]);
        __syncthreads();

        float* src = sy; float* dst = sy2;
        for (int l = 0; l < 3; l++) {
            float v[5];
#pragma unroll
            for (int j = 0; j < 5; j++) v[j] = s_ab[l * 20 + sh + j];
            for (int i2 = 0; i2 < 20; i2++) {
                float yv = src[a * 20 + i2];
#pragma unroll
                for (int j = 0; j < 5; j++) v[j] += yv * s_aw[(l * 20 + i2) * 20 + sh + j];
            }
            __syncthreads();
#pragma unroll
            for (int j = 0; j < 5; j++) dst[a * 20 + sh + j] = softplusf(v[j]);
            __syncthreads();
            float* tp = src; src = dst; dst = tp;
        }
#pragma unroll
        for (int j = 0; j < 5; j++) s_xcat[a * 40 + sh + j] = src[a * 20 + sh + j];
    }
    __syncthreads();

    // ---- phase 3: env (40 f) for my 32 atoms; s-split by q-parity ----
    {
        int qh = t >> 8;            // 0: q in {0,2,4}; 1: q in {1,3}
        int sub = t & 255;
        int i  = sub >> 3;
        int f0 = (sub & 7) * 5;
        u64t acc[3][2][5];
#pragma unroll
        for (int qi = 0; qi < 3; qi++)
#pragma unroll
            for (int hh = 0; hh < 2; hh++)
#pragma unroll
                for (int j = 0; j < 5; j++) acc[qi][hh][j] = 0ULL;
        const float* sen = s_work + i * SROW;
        const int* nbp = s_nb + i * 32;
        for (int k = 0; k < 32; k++) {
            int nb = nbp[k];
            const float* xr = s_xcat + nb * 40 + f0;
            u64t xd[5];
#pragma unroll
            for (int j = 0; j < 5; j++) xd[j] = packdup(xr[j]);
            const ulonglong2* sk = (const ulonglong2*)(sen + k * 20);
            int qi = 0;
            for (int q = qh; q < 5; q += 2, qi++) {
                ulonglong2 sv = sk[q];
#pragma unroll
                for (int j = 0; j < 5; j++) {
                    ffma2(acc[qi][0][j], sv.x, xd[j]);
                    ffma2(acc[qi][1][j], sv.y, xd[j]);
                }
            }
        }
        int qi = 0;
        for (int q = qh; q < 5; q += 2, qi++) {
#pragma unroll
            for (int j = 0; j < 5; j++) {
                s_envP[((2 * q)     * 40 + f0 + j) * EPS2 + i] = acc[qi][0][j];
                s_envP[((2 * q + 1) * 40 + f0 + j) * EPS2 + i] = acc[qi][1][j];
            }
        }
    }
    __syncthreads();

    // ---- phase 4: GEMM, K-split halves share each staged chunk ----
    u64t accA[5], accB[5];
#pragma unroll
    for (int j = 0; j < 5; j++) { accA[j] = 0ULL; accB[j] = 0ULL; }
    int kh  = t >> 8;
    int sub = t & 255;
    int g0 = (sub & 15) * 5;
    int i0 = (sub >> 4) * 2;
    const float4* W4 = (const float4*)g_wpair;

    for (int i = t; i < 2560; i += 512) ((float4*)s_wc)[i] = W4[i];
    __syncthreads();

    for (int c = 0; c < 7; c++) {
        int p0 = c * 64;
        int plen = (c < 6) ? 64 : 16;
        int half = plen >> 1;
        int pbeg = kh * half, pend = pbeg + half;
        float4 pf[5];
        int nb4 = 0, pbase = 0;
        if (c < 6) {
            nb4 = ((c + 1 < 6) ? 64 : 16) * 40;
            pbase = (p0 + 64) * 40;
#pragma unroll
            for (int q = 0; q < 5; q++) {
                int i = t + q * 512;
                if (i < nb4) pf[q] = W4[pbase + i];
            }
        }
        for (int pp = pbeg; pp < pend; pp++) {
            ulonglong2 av = *(const ulonglong2*)&s_envP[(p0 + pp) * EPS2 + i0];
            const u64t* wr = &s_wcu[pp * 80 + g0];
            u64t b0 = wr[0], b1 = wr[1], b2 = wr[2], b3 = wr[3], b4 = wr[4];
            ffma2(accA[0], av.x, b0); ffma2(accB[0], av.y, b0);
            ffma2(accA[1], av.x, b1); ffma2(accB[1], av.y, b1);
            ffma2(accA[2], av.x, b2); ffma2(accB[2], av.y, b2);
            ffma2(accA[3], av.x, b3); ffma2(accB[3], av.y, b3);
            ffma2(accA[4], av.x, b4); ffma2(accB[4], av.y, b4);
        }
        __syncthreads();
        if (c < 6) {
#pragma unroll
            for (int q = 0; q < 5; q++) {
                int i = t + q * 512;
                if (i < nb4) ((float4*)s_wc)[i] = pf[q];
            }
            __syncthreads();
        }
    }

    // kh0: self term + bias, write; then kh1 accumulates in
    if (kh == 0) {
        const u64t* xc0p = (const u64t*)(s_xcat + (L0 + i0) * 40);
        const u64t* xc1p = (const u64t*)(s_xcat + (L0 + i0 + 1) * 40);
        const u64t* wsp = (const u64t*)g_wspair;
#pragma unroll 4
        for (int fp = 0; fp < 20; fp++) {
            u64t a0p = xc0p[fp];
            u64t a1p = xc1p[fp];
            const u64t* wr = wsp + fp * 80 + g0;
#pragma unroll
            for (int j = 0; j < 5; j++) {
                u64t w = wr[j];
                ffma2(accA[j], a0p, w);
                ffma2(accB[j], a1p, w);
            }
        }
        float* d0 = &s_tmp[(i0 + 0) * 80 + g0];
        float* d1 = &s_tmp[(i0 + 1) * 80 + g0];
#pragma unroll
        for (int j = 0; j < 5; j++) {
            float b = Wb[g0 + j];
            float lo, hi;
            unpack2(accA[j], lo, hi);
            d0[j] = lo + hi + b;
            unpack2(accB[j], lo, hi);
            d1[j] = lo + hi + b;
        }
    }
    __syncthreads();
    if (kh == 1) {
        float* d0 = &s_tmp[(i0 + 0) * 80 + g0];
        float* d1 = &s_tmp[(i0 + 1) * 80 + g0];
#pragma unroll
        for (int j = 0; j < 5; j++) {
            float lo, hi;
            unpack2(accA[j], lo, hi);
            d0[j] += lo + hi;
            unpack2(accB[j], lo, hi);
            d1[j] += lo + hi;
        }
    }
    __syncthreads();

    // ---- phase 5: gates ----
    for (int idx = t; idx < TM * 20; idx += 512) {
        int i = idx / 20, j = idx % 20;
        int a = A0 + i;
        float t0v = s_tmp[i * 80 + j * 4 + 0];
        float t1v = s_tmp[i * 80 + j * 4 + 1];
        float t2v = s_tmp[i * 80 + j * 4 + 2];
        float t3v = s_tmp[i * 80 + j * 4 + 3];
        float o  = sigmoidf(t3v);
        float cn = sigmoidf(t1v) * g_ct[a * 20 + j] + sigmoidf(t0v) * tanhf(t2v);
        g_ct[a * 20 + j] = cn;
        h_w[a * 20 + j]  = o * tanhf(cn);
        s_o[i * 20 + j] = o;
    }
    __syncthreads();

    // ---- x0 epilogue ----
    if (t < TM) {
        int a = A0 + t;
        float x0v = pb1[0];
#pragma unroll
        for (int f = 0; f < 5; f++)  x0v += g_indf[a * 5 + f] * pw0[f];
#pragma unroll
        for (int j = 0; j < 20; j++) x0v += s_o[t * 20 + j] * pw1[j];
        x0_w[a] = x0v;
        if (outcol >= 0) out[a * 3 + outcol] = x0v;
    }
}

// ---------------- host ----------------
extern "C" void kernel_launch(void* const* d_in, const int* in_sizes, int n_in,
                              void* d_out, int out_size) {
    const int*   species = (const int*)d_in[0];
    const float* coords  = (const float*)d_in[1];
    const float* x_h     = (const float*)d_in[2];
    const float* x_raw   = (const float*)d_in[3];
    const int*   ps      = (const int*)d_in[5];
    const float* h0_iw   = (const float*)d_in[6];
    const float* h0_sw   = (const float*)d_in[7];
    const float* h0_sb   = (const float*)d_in[8];
    const float* h0_aw   = (const float*)d_in[9];
    const float* h0_ab   = (const float*)d_in[10];
    const float* h1_iw   = (const float*)d_in[11];
    const float* h1_sw   = (const float*)d_in[12];
    const float* h1_sb   = (const float*)d_in[13];
    const float* h1_aw   = (const float*)d_in[14];
    const float* h1_ab   = (const float*)d_in[15];
    const float* W_iw    = (const float*)d_in[16];
    const float* W_sw    = (const float*)d_in[17];
    const float* W_sb    = (const float*)d_in[18];
    const float* pw0     = (const float*)d_in[19];
    const float* pw1     = (const float*)d_in[20];
    const float* pb1     = (const float*)d_in[21];
    float* out = (float*)d_out;

    cudaFuncSetAttribute(k_step, cudaFuncAttributeMaxDynamicSharedMemorySize, SMEM_BYTES);
    cudaFuncSetAttribute(k_f0,   cudaFuncAttributeMaxDynamicSharedMemorySize, SMEM_F0_BYTES);

    k_prep<<<NPAIR / 256, 256>>>(species, x_h, coords, ps, W_iw, W_sw);
    k_f0<<<NTOT / TM, 256, SMEM_F0_BYTES>>>(ps, h0_iw, h0_sw, h0_sb, h0_aw, h0_ab);

    for (int s = 0; s < 5; s++) {
        int mode = (s < 2) ? s : 2;
        int outcol = (s >= 2) ? (s - 2) : -1;
        k_step<<<NTOT / TM, 512, SMEM_BYTES>>>(ps, x_raw, mode,
                                               h1_iw, h1_sw, h1_sb, h1_aw, h1_ab,
                                               W_sb,
                                               pw0, pw1, pb1,
                                               outcol, out, s & 1);
    }
}

// round 11
// speedup vs baseline: 1.2670x; 1.2670x over previous
#include <cuda_runtime.h>
#include <math.h>

#define NMOL   32
#define NATOM  128
#define DEG    32
#define NTOT   4096
#define NPAIR  131072
#define NSENS  20
#define NF1    20
#define TM     32          // atoms owned per k_step block
#define EPS2   34          // envP row stride in u64 units
#define SROW   648         // padded sense row (floats) = 162 float4

typedef unsigned long long u64t;

// ---------------- scratch (device globals; no allocation) ----------------
__device__ float  g_sense[NPAIR * NSENS];    // [pair][s]
__device__ float  g_indf [NTOT * 5];         // [atom][5]
__device__ float  g_ct   [NTOT * NF1];       // in-place (owner block only)
__device__ float  g_h    [2 * NTOT * NF1];   // parity double buffer
__device__ float  g_x0   [2 * NTOT];         // parity double buffer
__device__ float  g_xt   [NTOT * NF1];       // x_t written by k_xt, read by k_step
__device__ float2 g_wpair [400 * 80];        // Wint paired over (s_even, s_odd)
__device__ float2 g_wspair[20 * 80];         // Wself paired over (f_even, f_odd)

__device__ __forceinline__ float softplusf(float x) {
    return fmaxf(x, 0.f) + log1pf(expf(-fabsf(x)));
}
__device__ __forceinline__ float sigmoidf(float x) {
    return 1.f / (1.f + expf(-x));
}
__device__ __forceinline__ u64t packdup(float x) {
    u64t r; asm("mov.b64 %0, {%1, %1};" : "=l"(r) : "f"(x)); return r;
}
__device__ __forceinline__ void ffma2(u64t& d, u64t a, u64t b) {
    asm("fma.rn.f32x2 %0, %1, %2, %0;" : "+l"(d) : "l"(a), "l"(b));
}
__device__ __forceinline__ void fadd2(u64t& d, u64t a) {
    asm("add.rn.f32x2 %0, %0, %1;" : "+l"(d) : "l"(a));
}
__device__ __forceinline__ void unpack2(u64t v, float& lo, float& hi) {
    asm("mov.b64 {%0, %1}, %2;" : "=f"(lo), "=f"(hi) : "l"(v));
}

// ---------------- one-time prep: sense (smem-staged stores) + indf + weight pairing ----
__global__ void k_prep(const int* __restrict__ species, const float* __restrict__ x_h,
                       const float* __restrict__ coord, const int* __restrict__ ps,
                       const float* __restrict__ Wint, const float* __restrict__ Wself) {
    __shared__ float sbuf[256 * 20];
    int t = threadIdx.x;
    int p = blockIdx.x * 256 + t;   // [0, NPAIR)

    // ---- sense via anchored Gaussian recurrence into smem row ----
    {
        int a = p >> 5;
        int b = ps[p];
        float dx = coord[a * 3 + 0] - coord[b * 3 + 0];
        float dy = coord[a * 3 + 1] - coord[b * 3 + 1];
        float dz = coord[a * 3 + 2] - coord[b * 3 + 2];
        float d = sqrtf(dx * dx + dy * dy + dz * dz + 1e-12f);
        float cut = 0.f;
        if (d < 7.5f) { float c = cospif(d * (1.f / 15.f)); cut = c * c; }
        const float m0 = 0.2f;
        const float m1 = 1.f / 0.7f;
        const float invsig = 20.f / (m1 - m0);
        const float delta = 20.f / 19.f;
        float z0 = (1.f / d - m0) * invsig;

        float ss = floorf(z0 / delta + 0.5f);
        ss = fminf(fmaxf(ss, 0.f), 19.f);
        int sstar = (int)ss;
        float zs = z0 - ss * delta;

        float Cd = expf(-delta * delta);
        float E  = cut * expf(-0.5f * zs * zs);
        float* o = sbuf + t * 20;
        o[sstar] = E;
        float Eu = E;
        float uu = expf(delta * zs - 0.5f * delta * delta);
        for (int s = sstar + 1; s < 20; s++) { Eu *= uu; uu *= Cd; o[s] = Eu; }
        float Ed = E;
        float dd = expf(-delta * zs - 0.5f * delta * delta);
        for (int s = sstar - 1; s >= 0; s--) { Ed *= dd; dd *= Cd; o[s] = Ed; }
    }
    __syncthreads();
    {   // coalesced float4 store of the block's 5120 floats
        float4* dst = (float4*)(g_sense + (size_t)blockIdx.x * 5120);
        const float4* src = (const float4*)sbuf;
        for (int i = t; i < 1280; i += 256) dst[i] = src[i];
    }

    // ---- indf ----
    if (p < NTOT) {
        int sp = species[p];
        g_indf[p * 5 + 0] = (sp == 1) ? 1.f : 0.f;
        g_indf[p * 5 + 1] = (sp == 8) ? 1.f : 0.f;
        g_indf[p * 5 + 2] = x_h[p * 3 + 0];
        g_indf[p * 5 + 3] = x_h[p * 3 + 1];
        g_indf[p * 5 + 4] = x_h[p * 3 + 2];
    }

    // ---- weight pairing ----
    if (p < 32000) {
        int pr = p / 80, g = p % 80;
        int s2 = pr / 40, f = pr % 40;
        int lo = 2 * s2 * 40 + f;
        g_wpair[p] = make_float2(Wint[lo * 80 + g], Wint[(lo + 40) * 80 + g]);
    } else if (p < 32000 + 1600) {
        int i2 = p - 32000;
        int fp = i2 / 80, g = i2 % 80;
        g_wspair[i2] = make_float2(Wself[(2 * fp) * 80 + g], Wself[(2 * fp + 1) * 80 + g]);
    }
}

// ---------------- f0 hipnn (runs once, block-tiled): writes c_t, g_h[0] ----------------
#define SMEM_F0_FLOATS 37448
#define SMEM_F0_BYTES  (SMEM_F0_FLOATS * 4)

__global__ void __launch_bounds__(256, 1)
k_f0(const int* __restrict__ ps,
     const float* __restrict__ iw, const float* __restrict__ sw,
     const float* __restrict__ sb, const float* __restrict__ aw,
     const float* __restrict__ ab) {
    extern __shared__ float sm[];
    float* s_sense = sm;
    float* s_senv  = sm + 20736;
    float* s_indf  = sm + 24064;
    float* s_iw    = sm + 24704;
    float* s_sw    = sm + 28704;
    float* s_sb    = sm + 28904;
    float* s_aw    = sm + 28944;
    float* s_ab    = sm + 33744;
    float* s_sy    = sm + 33864;
    float* s_sy2   = sm + 35144;
    int*   s_nb    = (int*)(sm + 36424);

    int t  = threadIdx.x;
    int A0 = blockIdx.x * TM;
    int MB = (A0 / NATOM) * NATOM;
    int L0 = A0 - MB;

    for (int i = t; i < 1024; i += 256) s_nb[i] = ps[A0 * 32 + i] - MB;
    for (int i = t; i < 640;  i += 256) s_indf[i] = g_indf[MB * 5 + i];
    for (int i = t; i < 4000; i += 256) s_iw[i] = iw[i];
    for (int i = t; i < 4800; i += 256) s_aw[i] = aw[i];
    if (t < 200) s_sw[t] = sw[t];
    if (t >= 216 && t < 256) s_sb[t - 216] = sb[t - 216];
    for (int i = t; i < 120; i += 256) s_ab[i] = ab[i];
    {
        const float4* src = (const float4*)(g_sense + (size_t)A0 * 640);
        float4* dst = (float4*)s_sense;
        for (int q = 0; q < 20; q++) {
            int i = t + q * 256;
            int row = i / 160, col = i - row * 160;
            dst[row * 162 + col] = src[i];
        }
    }
    __syncthreads();

    {
        int aL = t >> 3;
        int r  = t & 7;
        u64t acc[10][5];
#pragma unroll
        for (int q = 0; q < 10; q++)
#pragma unroll
            for (int f = 0; f < 5; f++) acc[q][f] = 0ULL;
#pragma unroll
        for (int j = 0; j < 4; j++) {
            int k = r + j * 8;
            int nb = s_nb[aL * 32 + k];
            const float* xp = s_indf + nb * 5;
            u64t xd[5];
#pragma unroll
            for (int f = 0; f < 5; f++) xd[f] = packdup(xp[f]);
            const ulonglong2* spp = (const ulonglong2*)(s_sense + aL * SROW + k * 20);
#pragma unroll
            for (int q = 0; q < 5; q++) {
                ulonglong2 sv = spp[q];
#pragma unroll
                for (int f = 0; f < 5; f++) {
                    ffma2(acc[q * 2 + 0][f], sv.x, xd[f]);
                    ffma2(acc[q * 2 + 1][f], sv.y, xd[f]);
                }
            }
        }
#pragma unroll
        for (int d = 4; d >= 1; d >>= 1)
#pragma unroll
            for (int q = 0; q < 10; q++)
#pragma unroll
                for (int f = 0; f < 5; f++) {
                    u64t o = __shfl_down_sync(0xFFFFFFFFu, acc[q][f], d);
                    fadd2(acc[q][f], o);
                }
        if (r == 0) {
#pragma unroll
            for (int q = 0; q < 10; q++)
#pragma unroll
                for (int f = 0; f < 5; f++) {
                    float lo, hi;
                    unpack2(acc[q][f], lo, hi);
                    s_senv[aL * 104 + (2 * q)     * 5 + f] = lo;
                    s_senv[aL * 104 + (2 * q + 1) * 5 + f] = hi;
                }
        }
    }
    __syncthreads();

    {
        int a  = t >> 3;
        int j0 = (t & 7) * 5;
        float pre[5];
#pragma unroll
        for (int jj = 0; jj < 5; jj++) pre[jj] = s_sb[j0 + jj];
        const float* xo = s_indf + (L0 + a) * 5;
#pragma unroll
        for (int f = 0; f < 5; f++) {
            float xv = xo[f];
#pragma unroll
            for (int jj = 0; jj < 5; jj++) pre[jj] += xv * s_sw[f * 40 + j0 + jj];
        }
        for (int e = 0; e < 100; e++) {
            float ev = s_senv[a * 104 + e];
#pragma unroll
            for (int jj = 0; jj < 5; jj++) pre[jj] += ev * s_iw[e * 40 + j0 + jj];
        }
#pragma unroll
        for (int jj = 0; jj < 5; jj++) s_sy[a * 40 + j0 + jj] = softplusf(pre[jj]);
        __syncthreads();

        float* src = s_sy; float* dst = s_sy2;
        for (int l = 0; l < 3; l++) {
            float v[5];
#pragma unroll
            for (int jj = 0; jj < 5; jj++) v[jj] = s_ab[l * 40 + j0 + jj];
            for (int i = 0; i < 40; i++) {
                float yv = src[a * 40 + i];
#pragma unroll
                for (int jj = 0; jj < 5; jj++) v[jj] += yv * s_aw[l * 1600 + i * 40 + j0 + jj];
            }
            __syncthreads();
#pragma unroll
            for (int jj = 0; jj < 5; jj++) dst[a * 40 + j0 + jj] = softplusf(v[jj]);
            __syncthreads();
            float* tp = src; src = dst; dst = tp;
        }
        for (int idx = t; idx < 640; idx += 256) {
            int a2 = idx / 20, j = idx % 20;
            g_ct[(A0 + a2) * 20 + j] = src[a2 * 40 + j];
            g_h[(A0 + a2) * 20 + j]  = src[a2 * 40 + 20 + j];
        }
    }
}

// ---------------- per-step x_t kernel: own 32 atoms, computed once ----------------
__global__ void __launch_bounds__(256, 2)
k_xt(const int* __restrict__ ps, const float* __restrict__ x_raw, int mode,
     const float* __restrict__ h1_iw, const float* __restrict__ h1_sw,
     const float* __restrict__ h1_sb, const float* __restrict__ h1_aw,
     const float* __restrict__ h1_ab, int parity) {
    __shared__ float s_xin[128];
    __shared__ float s_iw[400], s_sw[20], s_sb[20], s_aw[1200], s_ab[60];
    __shared__ float s_env[640], s_y[640], s_y2[640];

    int t  = threadIdx.x;
    int A0 = blockIdx.x * TM;
    int MB = (A0 / NATOM) * NATOM;
    int L0 = A0 - MB;
    const float* x0_r = g_x0 + parity * NTOT;

    if (t < 128) {
        int n = MB + t;
        s_xin[t] = (mode < 2) ? x_raw[n * 2 + mode] : x0_r[n];
    }
    for (int i = t; i < 400;  i += 256) s_iw[i] = h1_iw[i];
    for (int i = t; i < 1200; i += 256) s_aw[i] = h1_aw[i];
    if (t >= 160 && t < 180) { s_sw[t - 160] = h1_sw[t - 160]; s_sb[t - 160] = h1_sb[t - 160]; }
    if (t >= 192 && t < 252) s_ab[t - 192] = h1_ab[t - 192];
    __syncthreads();

    // env for own 32 atoms: 8 k-lanes each, sense straight from global (L2-resident)
    {
        int i = t >> 3;
        int r = t & 7;
        int p0 = (A0 + i) * 32;
        u64t acc[10];
#pragma unroll
        for (int s = 0; s < 10; s++) acc[s] = 0ULL;
#pragma unroll
        for (int j = 0; j < 4; j++) {
            int k = r + j * 8;
            int p = p0 + k;
            int nb = ps[p] - MB;
            u64t xd = packdup(s_xin[nb]);
            const ulonglong2* sp = (const ulonglong2*)(g_sense + (size_t)p * 20);
#pragma unroll
            for (int q = 0; q < 5; q++) {
                ulonglong2 sv = sp[q];
                ffma2(acc[q * 2 + 0], sv.x, xd);
                ffma2(acc[q * 2 + 1], sv.y, xd);
            }
        }
#pragma unroll
        for (int d = 4; d >= 1; d >>= 1)
#pragma unroll
            for (int s = 0; s < 10; s++) {
                u64t o = __shfl_down_sync(0xFFFFFFFFu, acc[s], d, 8);
                fadd2(acc[s], o);
            }
        if (r == 0) {
#pragma unroll
            for (int s = 0; s < 10; s++) {
                float lo, hi;
                unpack2(acc[s], lo, hi);
                s_env[i * 20 + 2 * s]     = lo;
                s_env[i * 20 + 2 * s + 1] = hi;
            }
        }
    }
    __syncthreads();

    // MLP: 4 threads/atom (t < 128), 5 outputs each
    {
        int a  = t >> 2;          // 0..31 (t<128)
        int sh = (t & 3) * 5;
        bool act = (t < 128);
        if (act) {
            float xo = s_xin[L0 + a];
            float pre[5];
#pragma unroll
            for (int j = 0; j < 5; j++) pre[j] = s_sb[sh + j] + xo * s_sw[sh + j];
            for (int s2 = 0; s2 < 20; s2++) {
                float ev = s_env[a * 20 + s2];
#pragma unroll
                for (int j = 0; j < 5; j++) pre[j] += ev * s_iw[s2 * 20 + sh + j];
            }
#pragma unroll
            for (int j = 0; j < 5; j++) s_y[a * 20 + sh + j] = softplusf(pre[j]);
        }
        __syncthreads();

        float* src = s_y; float* dst = s_y2;
        for (int l = 0; l < 3; l++) {
            float v[5];
            if (act) {
#pragma unroll
                for (int j = 0; j < 5; j++) v[j] = s_ab[l * 20 + sh + j];
                for (int i2 = 0; i2 < 20; i2++) {
                    float yv = src[a * 20 + i2];
#pragma unroll
                    for (int j = 0; j < 5; j++) v[j] += yv * s_aw[(l * 20 + i2) * 20 + sh + j];
                }
            }
            __syncthreads();
            if (act) {
#pragma unroll
                for (int j = 0; j < 5; j++) dst[a * 20 + sh + j] = softplusf(v[j]);
            }
            __syncthreads();
            float* tp = src; src = dst; dst = tp;
        }
        if (act) {
#pragma unroll
            for (int j = 0; j < 5; j++) g_xt[(A0 + a) * 20 + sh + j] = src[a * 20 + sh + j];
        }
    }
}

// ---------------- fused per-step kernel: 256 threads, phases 3/4/gates only ----------
// SMEM (floats): s_xcat[0,5120) | s_envP[5120,32320) | s_work[32320,53056) | s_nb[53056,54080)
#define SMEM_FLOATS (5120 + 27200 + 32 * SROW + 1024)
#define SMEM_BYTES  (SMEM_FLOATS * 4)

__global__ void __launch_bounds__(256, 1)
k_step(const int* __restrict__ ps,
       const float* __restrict__ Wb,
       const float* __restrict__ pw0, const float* __restrict__ pw1,
       const float* __restrict__ pb1,
       int outcol, float* __restrict__ out, int parity) {
    extern __shared__ float sm[];
    float* s_xcat = sm;                                    // 5120
    float* s_envPf = sm + 5120;                            // 27200
    u64t*  s_envP  = (u64t*)s_envPf;
    float* s_work = sm + 32320;                            // 20736
    int*   s_nb   = (int*)(sm + 53056);                    // 1024 ints

    float* s_wc  = s_work;          // GEMM W chunk (10240 floats)
    u64t*  s_wcu = (u64t*)s_wc;
    float* s_tmp = s_work + 10240;  // 2560
    float* s_o   = s_work + 12800;  // 640

    int t  = threadIdx.x;
    int A0 = blockIdx.x * TM;
    int MB = (A0 / NATOM) * NATOM;
    int L0 = A0 - MB;
    float* h_w = g_h + (parity ^ 1) * (NTOT * NF1);
    const float* h_r = g_h + parity * (NTOT * NF1);
    float* x0_w = g_x0 + (parity ^ 1) * NTOT;

    // ---- stage: xcat (x_t + h for whole molecule), nb, sense tile (own atoms) ----
    {
        const float4* xsrc = (const float4*)(g_xt + MB * NF1);
        const float4* hsrc = (const float4*)(h_r + MB * NF1);
        for (int i4 = t; i4 < 640; i4 += 256) {
            int a = i4 / 5, j = (i4 % 5) * 4;
            *(float4*)&s_xcat[a * 40 + j]      = xsrc[i4];
            *(float4*)&s_xcat[a * 40 + 20 + j] = hsrc[i4];
        }
    }
    for (int i = t; i < 1024; i += 256) s_nb[i] = ps[A0 * 32 + i] - MB;
    {
        const float4* src = (const float4*)(g_sense + (size_t)A0 * 640);
        float4* dst = (float4*)s_work;
        for (int q = 0; q < 20; q++) {
            int i = t + q * 256;
            int row = i / 160, col = i - row * 160;
            dst[row * 162 + col] = src[i];
        }
    }
    __syncthreads();

    // ---- phase 3: env (40 f) for my 32 atoms, packed s-pairs -> envP ----
    {
        int i  = t >> 3;
        int f0 = (t & 7) * 5;
        u64t acc[10][5];
#pragma unroll
        for (int sp = 0; sp < 10; sp++)
#pragma unroll
            for (int j = 0; j < 5; j++) acc[sp][j] = 0ULL;
        const float* sen = s_work + i * SROW;
        const int* nbp = s_nb + i * 32;
        for (int k = 0; k < 32; k++) {
            int nb = nbp[k];
            const float* xr = s_xcat + nb * 40 + f0;
            u64t xd[5];
#pragma unroll
            for (int j = 0; j < 5; j++) xd[j] = packdup(xr[j]);
            const ulonglong2* sk = (const ulonglong2*)(sen + k * 20);
#pragma unroll
            for (int q = 0; q < 5; q++) {
                ulonglong2 sv = sk[q];
#pragma unroll
                for (int j = 0; j < 5; j++) {
                    ffma2(acc[q * 2 + 0][j], sv.x, xd[j]);
                    ffma2(acc[q * 2 + 1][j], sv.y, xd[j]);
                }
            }
        }
#pragma unroll
        for (int sp = 0; sp < 10; sp++)
#pragma unroll
            for (int j = 0; j < 5; j++)
                s_envP[(sp * 40 + f0 + j) * EPS2 + i] = acc[sp][j];
    }
    __syncthreads();   // sense reads done + envP visible; s_work free for s_wc

    // ---- phase 4: GEMM, unroll-2 inner loop ----
    u64t accA[5], accB[5];
#pragma unroll
    for (int j = 0; j < 5; j++) { accA[j] = 0ULL; accB[j] = 0ULL; }
    int g0 = (t & 15) * 5;
    int i0 = (t >> 4) * 2;
    const float4* W4 = (const float4*)g_wpair;

    for (int i = t; i < 2560; i += 256) ((float4*)s_wc)[i] = W4[i];
    __syncthreads();

    for (int c = 0; c < 7; c++) {
        int p0 = c * 64;
        int plen = (c < 6) ? 64 : 16;
        float4 pf[10];
        int nb4 = 0, pbase = 0;
        if (c < 6) {
            nb4 = ((c + 1 < 6) ? 64 : 16) * 40;
            pbase = (p0 + 64) * 40;
#pragma unroll
            for (int q = 0; q < 10; q++) {
                int i = t + q * 256;
                if (i < nb4) pf[q] = W4[pbase + i];
            }
        }
        for (int pp = 0; pp < plen; pp += 2) {
            ulonglong2 av0 = *(const ulonglong2*)&s_envP[(p0 + pp) * EPS2 + i0];
            ulonglong2 av1 = *(const ulonglong2*)&s_envP[(p0 + pp + 1) * EPS2 + i0];
            const u64t* wr0 = &s_wcu[pp * 80 + g0];
            const u64t* wr1 = wr0 + 80;
            u64t w00 = wr0[0], w01 = wr0[1], w02 = wr0[2], w03 = wr0[3], w04 = wr0[4];
            u64t w10 = wr1[0], w11 = wr1[1], w12 = wr1[2], w13 = wr1[3], w14 = wr1[4];
            ffma2(accA[0], av0.x, w00); ffma2(accB[0], av0.y, w00);
            ffma2(accA[1], av0.x, w01); ffma2(accB[1], av0.y, w01);
            ffma2(accA[2], av0.x, w02); ffma2(accB[2], av0.y, w02);
            ffma2(accA[3], av0.x, w03); ffma2(accB[3], av0.y, w03);
            ffma2(accA[4], av0.x, w04); ffma2(accB[4], av0.y, w04);
            ffma2(accA[0], av1.x, w10); ffma2(accB[0], av1.y, w10);
            ffma2(accA[1], av1.x, w11); ffma2(accB[1], av1.y, w11);
            ffma2(accA[2], av1.x, w12); ffma2(accB[2], av1.y, w12);
            ffma2(accA[3], av1.x, w13); ffma2(accB[3], av1.y, w13);
            ffma2(accA[4], av1.x, w14); ffma2(accB[4], av1.y, w14);
        }
        __syncthreads();
        if (c < 6) {
#pragma unroll
            for (int q = 0; q < 10; q++) {
                int i = t + q * 256;
                if (i < nb4) ((float4*)s_wc)[i] = pf[q];
            }
            __syncthreads();
        }
    }

    // self term: packed f-pairs from xcat x g_wspair
    {
        const u64t* xc0p = (const u64t*)(s_xcat + (L0 + i0) * 40);
        const u64t* xc1p = (const u64t*)(s_xcat + (L0 + i0 + 1) * 40);
        const u64t* wsp = (const u64t*)g_wspair;
#pragma unroll 4
        for (int fp = 0; fp < 20; fp++) {
            u64t a0p = xc0p[fp];
            u64t a1p = xc1p[fp];
            const u64t* wr = wsp + fp * 80 + g0;
#pragma unroll
            for (int j = 0; j < 5; j++) {
                u64t w = wr[j];
                ffma2(accA[j], a0p, w);
                ffma2(accB[j], a1p, w);
            }
        }
    }

    // unpack + bias -> s_tmp
    {
        float* d0 = &s_tmp[(i0 + 0) * 80 + g0];
        float* d1 = &s_tmp[(i0 + 1) * 80 + g0];
#pragma unroll
        for (int j = 0; j < 5; j++) {
            float b = Wb[g0 + j];
            float lo, hi;
            unpack2(accA[j], lo, hi);
            d0[j] = lo + hi + b;
            unpack2(accB[j], lo, hi);
            d1[j] = lo + hi + b;
        }
    }
    __syncthreads();

    // ---- gates ----
    for (int idx = t; idx < TM * 20; idx += 256) {
        int i = idx / 20, j = idx % 20;
        int a = A0 + i;
        float t0v = s_tmp[i * 80 + j * 4 + 0];
        float t1v = s_tmp[i * 80 + j * 4 + 1];
        float t2v = s_tmp[i * 80 + j * 4 + 2];
        float t3v = s_tmp[i * 80 + j * 4 + 3];
        float o  = sigmoidf(t3v);
        float cn = sigmoidf(t1v) * g_ct[a * 20 + j] + sigmoidf(t0v) * tanhf(t2v);
        g_ct[a * 20 + j] = cn;
        h_w[a * 20 + j]  = o * tanhf(cn);
        s_o[i * 20 + j] = o;
    }
    __syncthreads();

    // ---- x0 epilogue ----
    if (t < TM) {
        int a = A0 + t;
        float x0v = pb1[0];
#pragma unroll
        for (int f = 0; f < 5; f++)  x0v += g_indf[a * 5 + f] * pw0[f];
#pragma unroll
        for (int j = 0; j < 20; j++) x0v += s_o[t * 20 + j] * pw1[j];
        x0_w[a] = x0v;
        if (outcol >= 0) out[a * 3 + outcol] = x0v;
    }
}

// ---------------- host ----------------
extern "C" void kernel_launch(void* const* d_in, const int* in_sizes, int n_in,
                              void* d_out, int out_size) {
    const int*   species = (const int*)d_in[0];
    const float* coords  = (const float*)d_in[1];
    const float* x_h     = (const float*)d_in[2];
    const float* x_raw   = (const float*)d_in[3];
    const int*   ps      = (const int*)d_in[5];
    const float* h0_iw   = (const float*)d_in[6];
    const float* h0_sw   = (const float*)d_in[7];
    const float* h0_sb   = (const float*)d_in[8];
    const float* h0_aw   = (const float*)d_in[9];
    const float* h0_ab   = (const float*)d_in[10];
    const float* h1_iw   = (const float*)d_in[11];
    const float* h1_sw   = (const float*)d_in[12];
    const float* h1_sb   = (const float*)d_in[13];
    const float* h1_aw   = (const float*)d_in[14];
    const float* h1_ab   = (const float*)d_in[15];
    const float* W_iw    = (const float*)d_in[16];
    const float* W_sw    = (const float*)d_in[17];
    const float* W_sb    = (const float*)d_in[18];
    const float* pw0     = (const float*)d_in[19];
    const float* pw1     = (const float*)d_in[20];
    const float* pb1     = (const float*)d_in[21];
    float* out = (float*)d_out;

    cudaFuncSetAttribute(k_step, cudaFuncAttributeMaxDynamicSharedMemorySize, SMEM_BYTES);
    cudaFuncSetAttribute(k_f0,   cudaFuncAttributeMaxDynamicSharedMemorySize, SMEM_F0_BYTES);

    k_prep<<<NPAIR / 256, 256>>>(species, x_h, coords, ps, W_iw, W_sw);
    k_f0<<<NTOT / TM, 256, SMEM_F0_BYTES>>>(ps, h0_iw, h0_sw, h0_sb, h0_aw, h0_ab);

    for (int s = 0; s < 5; s++) {
        int mode = (s < 2) ? s : 2;
        int outcol = (s >= 2) ? (s - 2) : -1;
        k_xt<<<NTOT / TM, 256>>>(ps, x_raw, mode,
                                 h1_iw, h1_sw, h1_sb, h1_aw, h1_ab, s & 1);
        k_step<<<NTOT / TM, 256, SMEM_BYTES>>>(ps, W_sb, pw0, pw1, pb1,
                                               outcol, out, s & 1);
    }
}